// round 1
// baseline (speedup 1.0000x reference)
#include <cuda_runtime.h>
#include <math.h>
#include <float.h>

// Problem dims (fixed by reference)
#define BDIM 8
#define SDIM 2048
#define EDIM 768
#define FFDIM 3072
#define NQDIM 128
#define RDIM (BDIM * SDIM)   // 16384 tokens

// ---------------------------------------------------------------------------
// Scratch (device globals; no runtime allocation allowed)
// ---------------------------------------------------------------------------
static __device__ float g_qa[(size_t)RDIM * EDIM];          // cos(x@Wp^T + th_rx)
static __device__ float g_scores[(size_t)BDIM * SDIM * SDIM]; // attention logits/probs
static __device__ float g_attn[(size_t)RDIM * EDIM];        // attn @ qa
static __device__ float g_x1[(size_t)RDIM * EDIM];          // LN1 output
static __device__ float g_qf[(size_t)RDIM * NQDIM];        // cos(x1[:,:128] + th_ry)
static __device__ float g_h[(size_t)RDIM * FFDIM];          // relu(qf@W1^T + b1)
static __device__ float g_y[(size_t)RDIM * EDIM];           // x1 + ffn + b2 (pre-LN2)

// ---------------------------------------------------------------------------
// Generic 128x128 tiled SGEMM, BK=8, 256 threads, 8x8 per-thread microtile.
//   BT=true : C = A(MxK) * B^T, B is NxK row-major (dot of rows)
//   BT=false: C = A(MxK) * B,   B is KxN row-major
// Epilogue MODE:
//   0: C = acc
//   1: C = cosf(acc + v1[n])
//   2: C = acc * scale
//   4: C = max(acc + v1[n], 0)
//   5: C = acc + v1[n] + add[m*N+n]
// All dims must be multiples of the tile (they are for this problem).
// ---------------------------------------------------------------------------
template <bool BT, int MODE>
__global__ void __launch_bounds__(256)
gemm128(const float* __restrict__ A, const float* __restrict__ Bm,
        float* __restrict__ C, int M, int N, int K,
        long sA, long sB, long sC,
        const float* __restrict__ v1, const float* __restrict__ add, float scale)
{
    __shared__ float As[8][128];
    __shared__ float Bs[8][128];

    const int bz = blockIdx.z;
    A  += (long)bz * sA;
    Bm += (long)bz * sB;
    C  += (long)bz * sC;

    const int n0 = blockIdx.x * 128;
    const int m0 = blockIdx.y * 128;
    const int tid = threadIdx.x;
    const int tx = tid & 15;          // 0..15  -> n micro position
    const int ty = tid >> 4;          // 0..15  -> m micro position
    const int la_m = tid >> 1;        // 0..127 (row within tile)
    const int la_k = (tid & 1) * 4;   // 0 or 4 (k offset, float4)
    const int lb_k = tid >> 5;        // 0..7   (NN: k row)
    const int lb_n = (tid & 31) * 4;  // 0..124 (NN: n offset, float4)

    float acc[8][8];
#pragma unroll
    for (int i = 0; i < 8; i++)
#pragma unroll
        for (int j = 0; j < 8; j++) acc[i][j] = 0.0f;

    for (int k0 = 0; k0 < K; k0 += 8) {
        // Load A tile (transpose into As[k][m])
        float4 av = *(const float4*)(A + (long)(m0 + la_m) * K + (k0 + la_k));
        As[la_k + 0][la_m] = av.x;
        As[la_k + 1][la_m] = av.y;
        As[la_k + 2][la_m] = av.z;
        As[la_k + 3][la_m] = av.w;

        if (BT) {
            float4 bv = *(const float4*)(Bm + (long)(n0 + la_m) * K + (k0 + la_k));
            Bs[la_k + 0][la_m] = bv.x;
            Bs[la_k + 1][la_m] = bv.y;
            Bs[la_k + 2][la_m] = bv.z;
            Bs[la_k + 3][la_m] = bv.w;
        } else {
            float4 bv = *(const float4*)(Bm + (long)(k0 + lb_k) * N + (n0 + lb_n));
            *(float4*)&Bs[lb_k][lb_n] = bv;
        }
        __syncthreads();

#pragma unroll
        for (int kk = 0; kk < 8; kk++) {
            float a[8], b[8];
            *(float4*)&a[0] = *(const float4*)&As[kk][ty * 8];
            *(float4*)&a[4] = *(const float4*)&As[kk][ty * 8 + 4];
            *(float4*)&b[0] = *(const float4*)&Bs[kk][tx * 8];
            *(float4*)&b[4] = *(const float4*)&Bs[kk][tx * 8 + 4];
#pragma unroll
            for (int i = 0; i < 8; i++)
#pragma unroll
                for (int j = 0; j < 8; j++)
                    acc[i][j] = fmaf(a[i], b[j], acc[i][j]);
        }
        __syncthreads();
    }

    // Epilogue
#pragma unroll
    for (int i = 0; i < 8; i++) {
        const int m = m0 + ty * 8 + i;
        const int nb = n0 + tx * 8;
        float* crow = C + (long)m * N + nb;
        float outv[8];
#pragma unroll
        for (int j = 0; j < 8; j++) {
            float v = acc[i][j];
            if (MODE == 1)      v = cosf(v + v1[nb + j]);
            else if (MODE == 2) v = v * scale;
            else if (MODE == 4) v = fmaxf(v + v1[nb + j], 0.0f);
            else if (MODE == 5) v = v + v1[nb + j] + add[(long)m * N + nb + j];
            outv[j] = v;
        }
        *(float4*)(crow)     = *(float4*)&outv[0];
        *(float4*)(crow + 4) = *(float4*)&outv[4];
    }
}

// ---------------------------------------------------------------------------
// Row softmax over length SDIM (2048). One 256-thread block per row.
// ---------------------------------------------------------------------------
__global__ void __launch_bounds__(256) softmax_kernel(float* __restrict__ sc)
{
    float* row = sc + (size_t)blockIdx.x * SDIM;
    const int t = threadIdx.x;
    __shared__ float red[256];

    float v[8];
    float mx = -FLT_MAX;
#pragma unroll
    for (int i = 0; i < 8; i++) {
        v[i] = row[t + i * 256];
        mx = fmaxf(mx, v[i]);
    }
    red[t] = mx;
    __syncthreads();
    for (int o = 128; o > 0; o >>= 1) {
        if (t < o) red[t] = fmaxf(red[t], red[t + o]);
        __syncthreads();
    }
    mx = red[0];
    __syncthreads();

    float sum = 0.0f;
#pragma unroll
    for (int i = 0; i < 8; i++) {
        v[i] = __expf(v[i] - mx);
        sum += v[i];
    }
    red[t] = sum;
    __syncthreads();
    for (int o = 128; o > 0; o >>= 1) {
        if (t < o) red[t] += red[t + o];
        __syncthreads();
    }
    const float inv = 1.0f / red[0];
#pragma unroll
    for (int i = 0; i < 8; i++) row[t + i * 256] = v[i] * inv;
}

// ---------------------------------------------------------------------------
// LN1: x1 = LN(x + attn) * g + b; also qf = cos(x1[:, :NQ] + theta_ry).
// One 256-thread block per row of 768.
// ---------------------------------------------------------------------------
__global__ void __launch_bounds__(256)
ln1_kernel(const float* __restrict__ x, const float* __restrict__ attn,
           float* __restrict__ x1, float* __restrict__ qf,
           const float* __restrict__ g, const float* __restrict__ b,
           const float* __restrict__ theta_ry)
{
    const long row = blockIdx.x;
    const float* xr = x + row * EDIM;
    const float* ar = attn + row * EDIM;
    const int t = threadIdx.x;
    __shared__ float s1[256], s2[256];

    float v[3];
    float sum = 0.0f, sumsq = 0.0f;
#pragma unroll
    for (int i = 0; i < 3; i++) {
        const int c = t + i * 256;
        const float val = xr[c] + ar[c];
        v[i] = val;
        sum += val;
        sumsq += val * val;
    }
    s1[t] = sum; s2[t] = sumsq;
    __syncthreads();
    for (int o = 128; o > 0; o >>= 1) {
        if (t < o) { s1[t] += s1[t + o]; s2[t] += s2[t + o]; }
        __syncthreads();
    }
    const float mean = s1[0] * (1.0f / EDIM);
    const float var = s2[0] * (1.0f / EDIM) - mean * mean;
    const float rstd = rsqrtf(var + 1e-5f);
#pragma unroll
    for (int i = 0; i < 3; i++) {
        const int c = t + i * 256;
        const float y = (v[i] - mean) * rstd * g[c] + b[c];
        x1[row * EDIM + c] = y;
        if (c < NQDIM) qf[row * NQDIM + c] = cosf(y + theta_ry[c]);
    }
}

// ---------------------------------------------------------------------------
// LN2: out = LN(y) * g + b, y = x1 + ffn + b2 already summed in GEMM epilogue.
// ---------------------------------------------------------------------------
__global__ void __launch_bounds__(256)
ln2_kernel(const float* __restrict__ y, float* __restrict__ out,
           const float* __restrict__ g, const float* __restrict__ b)
{
    const long row = blockIdx.x;
    const float* yr = y + row * EDIM;
    const int t = threadIdx.x;
    __shared__ float s1[256], s2[256];

    float v[3];
    float sum = 0.0f, sumsq = 0.0f;
#pragma unroll
    for (int i = 0; i < 3; i++) {
        const int c = t + i * 256;
        const float val = yr[c];
        v[i] = val;
        sum += val;
        sumsq += val * val;
    }
    s1[t] = sum; s2[t] = sumsq;
    __syncthreads();
    for (int o = 128; o > 0; o >>= 1) {
        if (t < o) { s1[t] += s1[t + o]; s2[t] += s2[t + o]; }
        __syncthreads();
    }
    const float mean = s1[0] * (1.0f / EDIM);
    const float var = s2[0] * (1.0f / EDIM) - mean * mean;
    const float rstd = rsqrtf(var + 1e-5f);
#pragma unroll
    for (int i = 0; i < 3; i++) {
        const int c = t + i * 256;
        out[row * EDIM + c] = (v[i] - mean) * rstd * g[c] + b[c];
    }
}

// ---------------------------------------------------------------------------
// Launch
// ---------------------------------------------------------------------------
extern "C" void kernel_launch(void* const* d_in, const int* in_sizes, int n_in,
                              void* d_out, int out_size)
{
    (void)in_sizes; (void)n_in; (void)out_size;
    const float* x        = (const float*)d_in[0];
    const float* Wp       = (const float*)d_in[1];
    const float* theta_rx = (const float*)d_in[2];
    const float* theta_ry = (const float*)d_in[3];
    const float* W1       = (const float*)d_in[4];
    const float* b1       = (const float*)d_in[5];
    const float* W2       = (const float*)d_in[6];
    const float* b2       = (const float*)d_in[7];
    const float* ln1_g    = (const float*)d_in[8];
    const float* ln1_b    = (const float*)d_in[9];
    const float* ln2_g    = (const float*)d_in[10];
    const float* ln2_b    = (const float*)d_in[11];
    float* out = (float*)d_out;

    float *p_qa, *p_sc, *p_at, *p_x1, *p_qf, *p_h, *p_y;
    cudaGetSymbolAddress((void**)&p_qa, g_qa);
    cudaGetSymbolAddress((void**)&p_sc, g_scores);
    cudaGetSymbolAddress((void**)&p_at, g_attn);
    cudaGetSymbolAddress((void**)&p_x1, g_x1);
    cudaGetSymbolAddress((void**)&p_qf, g_qf);
    cudaGetSymbolAddress((void**)&p_h, g_h);
    cudaGetSymbolAddress((void**)&p_y, g_y);

    const dim3 blk(256);

    // K1: qa = cos(x @ Wp^T + theta_rx)   [16384 x 768, K=768]
    gemm128<true, 1><<<dim3(EDIM / 128, RDIM / 128, 1), blk>>>(
        x, Wp, p_qa, RDIM, EDIM, EDIM, 0, 0, 0, theta_rx, nullptr, 0.0f);

    // K2: scores_b = (qa_b @ qa_b^T) / sqrt(8)   [per batch 2048 x 2048, K=768]
    gemm128<true, 2><<<dim3(SDIM / 128, SDIM / 128, BDIM), blk>>>(
        p_qa, p_qa, p_sc, SDIM, SDIM, EDIM,
        (long)SDIM * EDIM, (long)SDIM * EDIM, (long)SDIM * SDIM,
        nullptr, nullptr, 0.35355339059327373f /* 1/sqrt(8) */);

    // K3: softmax rows
    softmax_kernel<<<BDIM * SDIM, blk>>>(p_sc);

    // K4: attn_out_b = attn_b @ qa_b   [2048 x 768, K=2048]  (NN)
    gemm128<false, 0><<<dim3(EDIM / 128, SDIM / 128, BDIM), blk>>>(
        p_sc, p_qa, p_at, SDIM, EDIM, SDIM,
        (long)SDIM * SDIM, (long)SDIM * EDIM, (long)SDIM * EDIM,
        nullptr, nullptr, 0.0f);

    // K5: x1 = LN(x + attn_out), qf = cos(x1[:, :128] + theta_ry)
    ln1_kernel<<<RDIM, blk>>>(x, p_at, p_x1, p_qf, ln1_g, ln1_b, theta_ry);

    // K7: h = relu(qf @ W1^T + b1)   [16384 x 3072, K=128]
    gemm128<true, 4><<<dim3(FFDIM / 128, RDIM / 128, 1), blk>>>(
        p_qf, W1, p_h, RDIM, FFDIM, NQDIM, 0, 0, 0, b1, nullptr, 0.0f);

    // K8: y = h @ W2^T + b2 + x1   [16384 x 768, K=3072]
    gemm128<true, 5><<<dim3(EDIM / 128, RDIM / 128, 1), blk>>>(
        p_h, W2, p_y, RDIM, EDIM, FFDIM, 0, 0, 0, b2, p_x1, 0.0f);

    // K9: out = LN(y)
    ln2_kernel<<<RDIM, blk>>>(p_y, out, ln2_g, ln2_b);
}

// round 6
// speedup vs baseline: 5.7749x; 5.7749x over previous
#include <cuda_runtime.h>
#include <cuda_bf16.h>
#include <math.h>
#include <float.h>
#include <stdint.h>

#define BDIM 8
#define SDIM 2048
#define EDIM 768
#define FFDIM 3072
#define NQDIM 128
#define RDIM (BDIM * SDIM)   // 16384

// ---------------------------------------------------------------------------
// Scratch (device globals; aligned for vector/cp.async access)
// ---------------------------------------------------------------------------
static __device__ __align__(256) __nv_bfloat16 g_xb [(size_t)RDIM * EDIM];
static __device__ __align__(256) __nv_bfloat16 g_Wpb[(size_t)EDIM * EDIM];
static __device__ __align__(256) __nv_bfloat16 g_W1b[(size_t)FFDIM * NQDIM];
static __device__ __align__(256) __nv_bfloat16 g_W2b[(size_t)EDIM * FFDIM];
static __device__ __align__(256) __nv_bfloat16 g_qa [(size_t)RDIM * EDIM];
static __device__ __align__(256) __nv_bfloat16 g_qaT[(size_t)RDIM * EDIM];
static __device__ __align__(256) float         g_scores[(size_t)BDIM * SDIM * SDIM];
static __device__ __align__(256) __nv_bfloat16 g_P  [(size_t)BDIM * SDIM * SDIM];
static __device__ __align__(256) float         g_attn[(size_t)RDIM * EDIM];
static __device__ __align__(256) float         g_x1 [(size_t)RDIM * EDIM];
static __device__ __align__(256) __nv_bfloat16 g_qf [(size_t)RDIM * NQDIM];
static __device__ __align__(256) __nv_bfloat16 g_h  [(size_t)RDIM * FFDIM];
static __device__ __align__(256) float         g_y  [(size_t)RDIM * EDIM];

// ---------------------------------------------------------------------------
// PTX helpers (base ISA only: cp.async / ldmatrix / mma.sync are compute_100-safe)
// ---------------------------------------------------------------------------
static __device__ __forceinline__ uint32_t smem_u32(const void* p) {
    uint32_t a;
    asm("{ .reg .u64 t; cvta.to.shared.u64 t, %1; cvt.u32.u64 %0, t; }"
        : "=r"(a) : "l"(p));
    return a;
}

static __device__ __forceinline__ void cpasync16(uint32_t dst, const void* src) {
    asm volatile("cp.async.cg.shared.global [%0], [%1], 16;"
                 :: "r"(dst), "l"(__cvta_generic_to_global(src)));
}
#define CP_COMMIT() asm volatile("cp.async.commit_group;" ::: "memory")
#define CP_WAIT1()  asm volatile("cp.async.wait_group 1;" ::: "memory")

static __device__ __forceinline__ void ldsm4(uint32_t (&r)[4], uint32_t addr) {
    asm volatile("ldmatrix.sync.aligned.m8n8.x4.shared.b16 {%0,%1,%2,%3}, [%4];"
                 : "=r"(r[0]), "=r"(r[1]), "=r"(r[2]), "=r"(r[3]) : "r"(addr));
}

static __device__ __forceinline__ void mma16816(float (&d)[4], const uint32_t (&a)[4],
                                                uint32_t b0, uint32_t b1) {
    asm volatile(
        "mma.sync.aligned.m16n8k16.row.col.f32.bf16.bf16.f32 "
        "{%0,%1,%2,%3},{%4,%5,%6,%7},{%8,%9},{%0,%1,%2,%3};"
        : "+f"(d[0]), "+f"(d[1]), "+f"(d[2]), "+f"(d[3])
        : "r"(a[0]), "r"(a[1]), "r"(a[2]), "r"(a[3]), "r"(b0), "r"(b1));
}

// ---------------------------------------------------------------------------
// bf16 warp-MMA GEMM: C[M,N] = A[M,K] @ B[N,K]^T (both k-major), fp32 accum.
// Tile 128x128x64, 256 threads (8 warps, 2x4), 3-stage cp.async pipeline.
// Swizzle: 16B chunk c of row r stored at chunk (c ^ (r&7)).
// MODE: 0 fp32 raw; 1 bf16 cos(acc+v1[n]); 2 fp32 acc*scale;
//       4 bf16 relu(acc+v1[n]); 5 fp32 acc+v1[n]+add[m*N+n]
// ---------------------------------------------------------------------------
#define STAGES 3
#define STAGE_BYTES 32768           // 16KB A + 16KB B
#define SMEM_DYN (STAGES * STAGE_BYTES)

template <int MODE, typename OutT>
__global__ void __launch_bounds__(256, 1)
gemm_mma(const __nv_bfloat16* __restrict__ A, const __nv_bfloat16* __restrict__ B,
         OutT* __restrict__ C, int N, int K,
         long sA, long sB, long sC,
         const float* __restrict__ v1, const float* __restrict__ add, float scale)
{
    extern __shared__ char smem[];
    const uint32_t sb = smem_u32(smem);

    const int bz = blockIdx.z;
    A += (long)bz * sA;
    B += (long)bz * sB;
    C += (long)bz * sC;

    const int tid  = threadIdx.x;
    const int wid  = tid >> 5;
    const int lane = tid & 31;
    const int wm   = wid >> 2;       // 0..1
    const int wn   = wid & 3;        // 0..3
    const int m0   = blockIdx.y << 7;
    const int n0   = blockIdx.x << 7;
    const int KT   = K >> 6;

    // ---- stage loader (all 256 threads; 4 chunks A + 4 chunks B each) ----
    auto load_stage = [&](int stage, int kt) {
        const uint32_t As = sb + stage * STAGE_BYTES;
        const uint32_t Bs = As + 16384;
        const int k0 = kt << 6;
        #pragma unroll
        for (int i = 0; i < 4; i++) {
            const int lin = tid + i * 256;
            const int row = lin >> 3;
            const int ch  = lin & 7;
            const uint32_t sw = (uint32_t)((ch ^ (row & 7)) << 4);
            cpasync16(As + row * 128 + sw, A + (long)(m0 + row) * K + k0 + ch * 8);
            cpasync16(Bs + row * 128 + sw, B + (long)(n0 + row) * K + k0 + ch * 8);
        }
    };

    float acc[4][4][4];
    #pragma unroll
    for (int i = 0; i < 4; i++)
        #pragma unroll
        for (int j = 0; j < 4; j++)
            #pragma unroll
            for (int q = 0; q < 4; q++) acc[i][j][q] = 0.0f;

    // prologue: prefetch 2 stages
    load_stage(0, 0); CP_COMMIT();
    if (KT > 1) load_stage(1, 1);
    CP_COMMIT();

    // ldmatrix address pieces (lane-dependent, stage-independent)
    const int a_row  = wm * 64 + (lane & 15);          // + mt*16
    const int a_half = lane >> 4;                      // k-halfchunk
    const int b_row  = wn * 32 + ((lane >> 4) << 3) + (lane & 7);  // + np*16
    const int b_half = (lane >> 3) & 1;

    for (int kt = 0; kt < KT; kt++) {
        CP_WAIT1();
        __syncthreads();
        if (kt + 2 < KT) load_stage((kt + 2) % STAGES, kt + 2);
        CP_COMMIT();

        const uint32_t As = sb + (kt % STAGES) * STAGE_BYTES;
        const uint32_t Bs = As + 16384;

        #pragma unroll
        for (int kk = 0; kk < 4; kk++) {
            uint32_t a[4][4];
            #pragma unroll
            for (int mt = 0; mt < 4; mt++) {
                const int row = a_row + mt * 16;
                const uint32_t ch = (uint32_t)(((kk << 1) | a_half) ^ (row & 7));
                ldsm4(a[mt], As + row * 128 + (ch << 4));
            }
            uint32_t b[2][4];
            #pragma unroll
            for (int np = 0; np < 2; np++) {
                const int row = b_row + np * 16;
                const uint32_t ch = (uint32_t)(((kk << 1) | b_half) ^ (row & 7));
                ldsm4(b[np], Bs + row * 128 + (ch << 4));
            }
            #pragma unroll
            for (int mt = 0; mt < 4; mt++)
                #pragma unroll
                for (int nt = 0; nt < 4; nt++)
                    mma16816(acc[mt][nt], a[mt], b[nt >> 1][(nt & 1) * 2],
                             b[nt >> 1][(nt & 1) * 2 + 1]);
        }
        __syncthreads();
    }

    // ---- epilogue ----
    const int gid = lane >> 2;      // row group 0..7
    const int tig = lane & 3;       // col pair 0..3
    #pragma unroll
    for (int nt = 0; nt < 4; nt++) {
        const int col = n0 + wn * 32 + nt * 8 + tig * 2;
        float bias0 = 0.0f, bias1 = 0.0f;
        if (MODE == 1 || MODE == 4 || MODE == 5) {
            bias0 = __ldg(v1 + col);
            bias1 = __ldg(v1 + col + 1);
        }
        #pragma unroll
        for (int mt = 0; mt < 4; mt++) {
            #pragma unroll
            for (int h = 0; h < 2; h++) {   // h=0: rows gid, h=1: rows gid+8
                const int row = m0 + wm * 64 + mt * 16 + gid + h * 8;
                float f0 = acc[mt][nt][2 * h];
                float f1 = acc[mt][nt][2 * h + 1];
                if (MODE == 1) { f0 = cosf(f0 + bias0); f1 = cosf(f1 + bias1); }
                else if (MODE == 2) { f0 *= scale; f1 *= scale; }
                else if (MODE == 4) { f0 = fmaxf(f0 + bias0, 0.0f); f1 = fmaxf(f1 + bias1, 0.0f); }
                else if (MODE == 5) {
                    const float* ar = add + (long)row * N + col;
                    f0 = f0 + bias0 + ar[0];
                    f1 = f1 + bias1 + ar[1];
                }
                if (sizeof(OutT) == 4) {
                    float2* p = (float2*)((float*)C + (long)row * N + col);
                    *p = make_float2(f0, f1);
                } else {
                    uint32_t pk;
                    asm("cvt.rn.satfinite.bf16x2.f32 %0, %1, %2;"
                        : "=r"(pk) : "f"(f1), "f"(f0));
                    *(uint32_t*)((__nv_bfloat16*)C + (long)row * N + col) = pk;
                }
            }
        }
    }
}

// ---------------------------------------------------------------------------
// Elementwise / reduction kernels
// ---------------------------------------------------------------------------
__global__ void __launch_bounds__(256)
cvt_kernel(const float* __restrict__ src, __nv_bfloat16* __restrict__ dst, long n4)
{
    long i = blockIdx.x * 256L + threadIdx.x;
    if (i >= n4) return;
    float4 f = ((const float4*)src)[i];
    uint32_t lo, hi;
    asm("cvt.rn.satfinite.bf16x2.f32 %0, %1, %2;" : "=r"(lo) : "f"(f.y), "f"(f.x));
    asm("cvt.rn.satfinite.bf16x2.f32 %0, %1, %2;" : "=r"(hi) : "f"(f.w), "f"(f.z));
    ((uint2*)dst)[i] = make_uint2(lo, hi);
}

__global__ void __launch_bounds__(256)
transpose_kernel(const __nv_bfloat16* __restrict__ qa, __nv_bfloat16* __restrict__ qaT)
{
    __shared__ __nv_bfloat16 t[32][33];
    const int b = blockIdx.z;
    const int s0 = blockIdx.x * 32, e0 = blockIdx.y * 32;
    const long base = (long)b * SDIM * EDIM;
    for (int i = threadIdx.y; i < 32; i += 8)
        t[i][threadIdx.x] = qa[base + (long)(s0 + i) * EDIM + e0 + threadIdx.x];
    __syncthreads();
    const long baseT = (long)b * EDIM * SDIM;
    for (int i = threadIdx.y; i < 32; i += 8)
        qaT[baseT + (long)(e0 + i) * SDIM + s0 + threadIdx.x] = t[threadIdx.x][i];
}

__global__ void __launch_bounds__(256)
softmax_kernel(const float* __restrict__ sc, __nv_bfloat16* __restrict__ P)
{
    const float* row = sc + (size_t)blockIdx.x * SDIM;
    __nv_bfloat16* prow = P + (size_t)blockIdx.x * SDIM;
    const int t = threadIdx.x;
    __shared__ float red[256];

    float v[8];
    float mx = -FLT_MAX;
    #pragma unroll
    for (int i = 0; i < 8; i++) { v[i] = row[t + i * 256]; mx = fmaxf(mx, v[i]); }
    red[t] = mx;
    __syncthreads();
    for (int o = 128; o > 0; o >>= 1) {
        if (t < o) red[t] = fmaxf(red[t], red[t + o]);
        __syncthreads();
    }
    mx = red[0];
    __syncthreads();
    float sum = 0.0f;
    #pragma unroll
    for (int i = 0; i < 8; i++) { v[i] = __expf(v[i] - mx); sum += v[i]; }
    red[t] = sum;
    __syncthreads();
    for (int o = 128; o > 0; o >>= 1) {
        if (t < o) red[t] += red[t + o];
        __syncthreads();
    }
    const float inv = 1.0f / red[0];
    #pragma unroll
    for (int i = 0; i < 8; i++) prow[t + i * 256] = __float2bfloat16(v[i] * inv);
}

__global__ void __launch_bounds__(256)
ln1_kernel(const float* __restrict__ x, const float* __restrict__ attn,
           float* __restrict__ x1, __nv_bfloat16* __restrict__ qf,
           const float* __restrict__ g, const float* __restrict__ b,
           const float* __restrict__ theta_ry)
{
    const long row = blockIdx.x;
    const float* xr = x + row * EDIM;
    const float* ar = attn + row * EDIM;
    const int t = threadIdx.x;
    __shared__ float s1[256], s2[256];

    float v[3];
    float sum = 0.0f, sq = 0.0f;
    #pragma unroll
    for (int i = 0; i < 3; i++) {
        const int c = t + i * 256;
        const float val = xr[c] + ar[c];
        v[i] = val; sum += val; sq += val * val;
    }
    s1[t] = sum; s2[t] = sq;
    __syncthreads();
    for (int o = 128; o > 0; o >>= 1) {
        if (t < o) { s1[t] += s1[t + o]; s2[t] += s2[t + o]; }
        __syncthreads();
    }
    const float mean = s1[0] * (1.0f / EDIM);
    const float var = s2[0] * (1.0f / EDIM) - mean * mean;
    const float rstd = rsqrtf(var + 1e-5f);
    #pragma unroll
    for (int i = 0; i < 3; i++) {
        const int c = t + i * 256;
        const float y = (v[i] - mean) * rstd * g[c] + b[c];
        x1[row * EDIM + c] = y;
        if (c < NQDIM) qf[row * NQDIM + c] = __float2bfloat16(cosf(y + theta_ry[c]));
    }
}

__global__ void __launch_bounds__(256)
ln2_kernel(const float* __restrict__ y, float* __restrict__ out,
           const float* __restrict__ g, const float* __restrict__ b)
{
    const long row = blockIdx.x;
    const float* yr = y + row * EDIM;
    const int t = threadIdx.x;
    __shared__ float s1[256], s2[256];

    float v[3];
    float sum = 0.0f, sq = 0.0f;
    #pragma unroll
    for (int i = 0; i < 3; i++) {
        const int c = t + i * 256;
        const float val = yr[c];
        v[i] = val; sum += val; sq += val * val;
    }
    s1[t] = sum; s2[t] = sq;
    __syncthreads();
    for (int o = 128; o > 0; o >>= 1) {
        if (t < o) { s1[t] += s1[t + o]; s2[t] += s2[t + o]; }
        __syncthreads();
    }
    const float mean = s1[0] * (1.0f / EDIM);
    const float var = s2[0] * (1.0f / EDIM) - mean * mean;
    const float rstd = rsqrtf(var + 1e-5f);
    #pragma unroll
    for (int i = 0; i < 3; i++) {
        const int c = t + i * 256;
        out[row * EDIM + c] = (v[i] - mean) * rstd * g[c] + b[c];
    }
}

// ---------------------------------------------------------------------------
extern "C" void kernel_launch(void* const* d_in, const int* in_sizes, int n_in,
                              void* d_out, int out_size)
{
    (void)in_sizes; (void)n_in; (void)out_size;
    const float* x        = (const float*)d_in[0];
    const float* Wp       = (const float*)d_in[1];
    const float* theta_rx = (const float*)d_in[2];
    const float* theta_ry = (const float*)d_in[3];
    const float* W1       = (const float*)d_in[4];
    const float* b1       = (const float*)d_in[5];
    const float* W2       = (const float*)d_in[6];
    const float* b2       = (const float*)d_in[7];
    const float* ln1_g    = (const float*)d_in[8];
    const float* ln1_b    = (const float*)d_in[9];
    const float* ln2_g    = (const float*)d_in[10];
    const float* ln2_b    = (const float*)d_in[11];
    float* out = (float*)d_out;

    // Idempotent attribute setup (no static guard; capture-safe, cheap)
    cudaFuncSetAttribute(gemm_mma<0, float>, cudaFuncAttributeMaxDynamicSharedMemorySize, SMEM_DYN);
    cudaFuncSetAttribute(gemm_mma<1, __nv_bfloat16>, cudaFuncAttributeMaxDynamicSharedMemorySize, SMEM_DYN);
    cudaFuncSetAttribute(gemm_mma<2, float>, cudaFuncAttributeMaxDynamicSharedMemorySize, SMEM_DYN);
    cudaFuncSetAttribute(gemm_mma<4, __nv_bfloat16>, cudaFuncAttributeMaxDynamicSharedMemorySize, SMEM_DYN);
    cudaFuncSetAttribute(gemm_mma<5, float>, cudaFuncAttributeMaxDynamicSharedMemorySize, SMEM_DYN);

    void *p_xb, *p_Wpb, *p_W1b, *p_W2b, *p_qa, *p_qaT, *p_sc, *p_P, *p_at, *p_x1, *p_qf, *p_h, *p_y;
    cudaGetSymbolAddress(&p_xb, g_xb);
    cudaGetSymbolAddress(&p_Wpb, g_Wpb);
    cudaGetSymbolAddress(&p_W1b, g_W1b);
    cudaGetSymbolAddress(&p_W2b, g_W2b);
    cudaGetSymbolAddress(&p_qa, g_qa);
    cudaGetSymbolAddress(&p_qaT, g_qaT);
    cudaGetSymbolAddress(&p_sc, g_scores);
    cudaGetSymbolAddress(&p_P, g_P);
    cudaGetSymbolAddress(&p_at, g_attn);
    cudaGetSymbolAddress(&p_x1, g_x1);
    cudaGetSymbolAddress(&p_qf, g_qf);
    cudaGetSymbolAddress(&p_h, g_h);
    cudaGetSymbolAddress(&p_y, g_y);

    // ---- fp32 -> bf16 conversions ----
    {
        long n4;
        n4 = (long)RDIM * EDIM / 4;
        cvt_kernel<<<(unsigned)((n4 + 255) / 256), 256>>>(x, (__nv_bfloat16*)p_xb, n4);
        n4 = (long)EDIM * EDIM / 4;
        cvt_kernel<<<(unsigned)((n4 + 255) / 256), 256>>>(Wp, (__nv_bfloat16*)p_Wpb, n4);
        n4 = (long)FFDIM * NQDIM / 4;
        cvt_kernel<<<(unsigned)((n4 + 255) / 256), 256>>>(W1, (__nv_bfloat16*)p_W1b, n4);
        n4 = (long)EDIM * FFDIM / 4;
        cvt_kernel<<<(unsigned)((n4 + 255) / 256), 256>>>(W2, (__nv_bfloat16*)p_W2b, n4);
    }

    // K1: qa = cos(xb @ Wpb^T + theta_rx)   [16384 x 768, K=768]
    gemm_mma<1, __nv_bfloat16><<<dim3(EDIM / 128, RDIM / 128, 1), 256, SMEM_DYN>>>(
        (const __nv_bfloat16*)p_xb, (const __nv_bfloat16*)p_Wpb, (__nv_bfloat16*)p_qa,
        EDIM, EDIM, 0, 0, 0, theta_rx, nullptr, 0.0f);

    // transpose qa -> qaT (per batch) for K4's B operand
    transpose_kernel<<<dim3(SDIM / 32, EDIM / 32, BDIM), dim3(32, 8)>>>(
        (const __nv_bfloat16*)p_qa, (__nv_bfloat16*)p_qaT);

    // K2: scores = (qa @ qa^T) / sqrt(8)   per-batch [2048 x 2048, K=768]
    gemm_mma<2, float><<<dim3(SDIM / 128, SDIM / 128, BDIM), 256, SMEM_DYN>>>(
        (const __nv_bfloat16*)p_qa, (const __nv_bfloat16*)p_qa, (float*)p_sc,
        SDIM, EDIM, (long)SDIM * EDIM, (long)SDIM * EDIM, (long)SDIM * SDIM,
        nullptr, nullptr, 0.35355339059327373f);

    // softmax rows -> P (bf16)
    softmax_kernel<<<BDIM * SDIM, 256>>>((const float*)p_sc, (__nv_bfloat16*)p_P);

    // K4: attn = P @ qa   per-batch [2048 x 768, K=2048]; B = qaT (NT form)
    gemm_mma<0, float><<<dim3(EDIM / 128, SDIM / 128, BDIM), 256, SMEM_DYN>>>(
        (const __nv_bfloat16*)p_P, (const __nv_bfloat16*)p_qaT, (float*)p_at,
        EDIM, SDIM, (long)SDIM * SDIM, (long)SDIM * EDIM, (long)SDIM * EDIM,
        nullptr, nullptr, 0.0f);

    // LN1 -> x1 (fp32), qf (bf16)
    ln1_kernel<<<RDIM, 256>>>(x, (const float*)p_at, (float*)p_x1,
                              (__nv_bfloat16*)p_qf, ln1_g, ln1_b, theta_ry);

    // K7: h = relu(qf @ W1^T + b1)   [16384 x 3072, K=128]
    gemm_mma<4, __nv_bfloat16><<<dim3(FFDIM / 128, RDIM / 128, 1), 256, SMEM_DYN>>>(
        (const __nv_bfloat16*)p_qf, (const __nv_bfloat16*)p_W1b, (__nv_bfloat16*)p_h,
        FFDIM, NQDIM, 0, 0, 0, b1, nullptr, 0.0f);

    // K8: y = h @ W2^T + b2 + x1   [16384 x 768, K=3072]
    gemm_mma<5, float><<<dim3(EDIM / 128, RDIM / 128, 1), 256, SMEM_DYN>>>(
        (const __nv_bfloat16*)p_h, (const __nv_bfloat16*)p_W2b, (float*)p_y,
        EDIM, FFDIM, 0, 0, 0, b2, (const float*)p_x1, 0.0f);

    // LN2 -> out
    ln2_kernel<<<RDIM, 256>>>((const float*)p_y, out, ln2_g, ln2_b);
}